// round 1
// baseline (speedup 1.0000x reference)
#include <cuda_runtime.h>

// StateSpaceDiffusionModel: y[b,h,:] = causal_conv(u[b,h,:], f[h,:])
// reduced exactly to a scalar order-64 IIR+FIR:
//   y_t = sum_{j=0..63} a_j y_{t-1-j} + sum_{i=0..63} c_i u_{t-i}
// a_j = w_j * P_j, c_i = k_i * P_i, derived from the companion matrix M.

#define HH 512
#define NN 64
#define BB 16
#define LL 2048

__device__ float g_a[HH * NN];
__device__ float g_c[HH * NN];

// ---------------- Kernel 1: per-head coefficients (trivial) ----------------
__global__ void coef_kernel(const float* __restrict__ k) {
    __shared__ float sh[NN];
    __shared__ float shd[NN];
    __shared__ float shP[NN];
    __shared__ float shsum;
    int h = blockIdx.x;
    int j = threadIdx.x;
    float kv = k[h * NN + j];
    float kc = fminf(fmaxf(kv, 1.0f / 16.0f), 1.0f);
    sh[j] = kc;
    __syncthreads();
    if (j == 0) {
        float s = 0.f;
        for (int i = 0; i < NN; i++) s += sh[i];
        shsum = s;
    }
    __syncthreads();
    float kn = kc / shsum;                       // L1-normalized clamped k (positive)
    float s = (j < NN - 1) ? (1.0f + kn) : kn;   // column L1 norm of (A + b k^T)
    float w = kn / s;                            // M[0, j]
    shd[j] = 1.0f / s;                           // M[j+1, j] (subdiagonal), j < 63
    __syncthreads();
    if (j == 0) {
        float P = 1.f;
        for (int i = 0; i < NN; i++) { shP[i] = P; P *= shd[i]; }  // P_i = prod_{m<i} d_m
    }
    __syncthreads();
    float Pj = shP[j];
    g_a[h * NN + j] = w * Pj;    // IIR taps
    g_c[h * NN + j] = kv * Pj;   // FIR taps (original k!)
}

// ---------------- packed f32x2 helpers ----------------
typedef unsigned long long ull;
__device__ __forceinline__ ull pack2(float lo, float hi) {
    ull r; asm("mov.b64 %0, {%1,%2};" : "=l"(r) : "f"(lo), "f"(hi)); return r;
}
__device__ __forceinline__ void unpack2(ull v, float& lo, float& hi) {
    asm("mov.b64 {%0,%1}, %2;" : "=f"(lo), "=f"(hi) : "l"(v));
}
__device__ __forceinline__ ull fma2(ull a, ull b, ull c) {
    ull d; asm("fma.rn.f32x2 %0, %1, %2, %3;" : "=l"(d) : "l"(a), "l"(b), "l"(c)); return d;
}

// ---------------- Kernel 2: fused transposed-form scan ----------------
// Transposed direct form II:
//   y_t = c_0 u_t + R[1] + Q[1]
//   Q[i] <- Q[i+1] + Acoef[i]*y_t   (Acoef[i] = a_{i-1}, i = 1..64)
//   R[i] <- R[i+1] + Ccoef[i]*u_t   (Ccoef[i] = c_i,     i = 1..63)
// Two timesteps fused per iteration -> shift-by-2 aligns with f32x2 pairs:
//   pair p = (slot 2p+1, slot 2p+2), p = 0..31
//   Q''_p = Q_{p+1} + Ae_p*y_t + Ao_p*y_{t+1}
//   Ae_p = (Acoef[2p+2], Acoef[2p+3]), Ao_p = (Acoef[2p+1], Acoef[2p+2])
// Mapping: warp = 8 sequences x 4 lanes; lane r holds pairs 8r..8r+7.
__global__ void __launch_bounds__(256, 1)
scan_kernel(const float* __restrict__ u, float* __restrict__ y) {
    int warp = blockIdx.x * (blockDim.x >> 5) + (threadIdx.x >> 5);
    int lane = threadIdx.x & 31;
    int g = lane >> 2;   // group (sequence) within warp
    int r = lane & 3;    // lane within group
    int seq = warp * 8 + g;           // 0..8191 ; b = seq/512, h = seq%512
    int h = seq & (HH - 1);
    const float* ubase = u + (size_t)seq * LL;
    float* ybase = y + (size_t)seq * LL;

    const float* ah = g_a + h * NN;
    const float* ch = g_c + h * NN;

    ull Ae[8], Ao[8], Ce[8], Co[8], Qp[8], Rp[8];
#pragma unroll
    for (int i = 0; i < 8; i++) {
        int p = r * 8 + i;
        // Acoef(idx) = (1<=idx<=64) ? a[idx-1] : 0 ; Ccoef(idx) = (1<=idx<=63) ? c[idx] : 0
        int i1 = 2 * p + 1, i2 = 2 * p + 2, i3 = 2 * p + 3;
        float A1 = (i1 <= 64) ? ah[i1 - 1] : 0.f;
        float A2 = (i2 <= 64) ? ah[i2 - 1] : 0.f;
        float A3 = (i3 <= 64) ? ah[i3 - 1] : 0.f;
        float C1 = (i1 <= 63) ? ch[i1] : 0.f;
        float C2 = (i2 <= 63) ? ch[i2] : 0.f;
        float C3 = (i3 <= 63) ? ch[i3] : 0.f;
        Ae[i] = pack2(A2, A3);
        Ao[i] = pack2(A1, A2);
        Ce[i] = pack2(C2, C3);
        Co[i] = pack2(C1, C2);
        Qp[i] = 0ull; Rp[i] = 0ull;
    }
    float c0h = ch[0], c1h = ch[1], a0h = ah[0];
    float QQ1 = 0.f, QQ2 = 0.f, RR1 = 0.f, RR2 = 0.f;  // leader's slot-1/2 scalars

    float2 cur = *(const float2*)(ubase);  // t = 0,1 (broadcast within group)
    for (int t = 0; t < LL; t += 2) {
        // boundary pair from next lane (old values); lane r==3 -> zero (slot 65/66)
        ull qn = __shfl_down_sync(0xffffffffu, Qp[0], 1);
        ull rn = __shfl_down_sync(0xffffffffu, Rp[0], 1);
        if (r == 3) { qn = 0ull; rn = 0ull; }

        float2 nxt = make_float2(0.f, 0.f);
        if (t + 2 < LL) nxt = *(const float2*)(ubase + t + 2);  // prefetch

        float u0 = cur.x, u1 = cur.y;
        // leader (r==0) computes both outputs from old slot-1/2 values
        float y0 = fmaf(c0h, u0, RR1 + QQ1);
        float y1 = fmaf(a0h, y0, fmaf(c1h, u0, fmaf(c0h, u1, RR2 + QQ2)));
        ull ypk = pack2(y0, y1);
        ypk = __shfl_sync(0xffffffffu, ypk, lane & ~3);  // broadcast within group
        float y0b, y1b; unpack2(ypk, y0b, y1b);
        ull y0pk = pack2(y0b, y0b), y1pk = pack2(y1b, y1b);
        ull u0pk = pack2(u0, u0), u1pk = pack2(u1, u1);

#pragma unroll
        for (int i = 0; i < 7; i++) {
            Qp[i] = fma2(Ae[i], y0pk, fma2(Ao[i], y1pk, Qp[i + 1]));
            Rp[i] = fma2(Ce[i], u0pk, fma2(Co[i], u1pk, Rp[i + 1]));
        }
        Qp[7] = fma2(Ae[7], y0pk, fma2(Ao[7], y1pk, qn));
        Rp[7] = fma2(Ce[7], u0pk, fma2(Co[7], u1pk, rn));

        unpack2(Qp[0], QQ1, QQ2);
        unpack2(Rp[0], RR1, RR2);

        if (r == 0) *(float2*)(ybase + t) = make_float2(y0, y1);
        cur = nxt;
    }
}

extern "C" void kernel_launch(void* const* d_in, const int* in_sizes, int n_in,
                              void* d_out, int out_size) {
    const float* u = (const float*)d_in[0];
    const float* k = (const float*)d_in[1];
    if (n_in >= 2 && in_sizes[0] == HH * NN) {  // defensive: swap if metadata order differs
        u = (const float*)d_in[1];
        k = (const float*)d_in[0];
    }
    float* y = (float*)d_out;

    coef_kernel<<<HH, NN>>>(k);
    // 8192 sequences, 8 per warp, 8 warps per 256-thread CTA -> 128 CTAs (single wave)
    scan_kernel<<<(BB * HH) / 64, 256>>>(u, y);
}

// round 2
// speedup vs baseline: 1.1810x; 1.1810x over previous
#include <cuda_runtime.h>

// StateSpaceDiffusionModel: y[b,h,:] = causal_conv(u[b,h,:], f[h,:])
// reduced exactly to a scalar order-64 IIR+FIR (transposed direct form II):
//   y_t = c0*u_t + S[1]
//   S[i] <- S[i+1] + A'[i]*y_t + C'[i]*u_t   (merged Q+R delay line, i=1..64)
// A'[i] = a_{i-1}, C'[i] = c_i (i<=63).  a_j = w_j*P_j, c_i = k_i*P_i from
// the companion matrix M of the reference.

#define HH 512
#define NN 64
#define BB 16
#define LL 2048

__device__ float g_a[HH * NN];
__device__ float g_c[HH * NN];

// ---------------- Kernel 1: per-head coefficients (trivial) ----------------
__global__ void coef_kernel(const float* __restrict__ k) {
    __shared__ float sh[NN];
    __shared__ float shd[NN];
    __shared__ float shP[NN];
    __shared__ float shsum;
    int h = blockIdx.x;
    int j = threadIdx.x;
    float kv = k[h * NN + j];
    float kc = fminf(fmaxf(kv, 1.0f / 16.0f), 1.0f);
    sh[j] = kc;
    __syncthreads();
    if (j == 0) {
        float s = 0.f;
        for (int i = 0; i < NN; i++) s += sh[i];
        shsum = s;
    }
    __syncthreads();
    float kn = kc / shsum;                       // L1-normalized clamped k
    float s = (j < NN - 1) ? (1.0f + kn) : kn;   // column L1 norm of (A + b k^T)
    float w = kn / s;                            // M[0, j]
    shd[j] = 1.0f / s;                           // M[j+1, j] subdiagonal
    __syncthreads();
    if (j == 0) {
        float P = 1.f;
        for (int i = 0; i < NN; i++) { shP[i] = P; P *= shd[i]; }
    }
    __syncthreads();
    float Pj = shP[j];
    g_a[h * NN + j] = w * Pj;    // IIR taps
    g_c[h * NN + j] = kv * Pj;   // FIR taps (original k!)
}

// ---------------- packed f32x2 helpers ----------------
typedef unsigned long long ull;
__device__ __forceinline__ ull pack2(float lo, float hi) {
    ull r; asm("mov.b64 %0, {%1,%2};" : "=l"(r) : "f"(lo), "f"(hi)); return r;
}
__device__ __forceinline__ void unpack2(ull v, float& lo, float& hi) {
    asm("mov.b64 {%0,%1}, %2;" : "=f"(lo), "=f"(hi) : "l"(v));
}
__device__ __forceinline__ ull fma2(ull a, ull b, ull c) {
    ull d; asm("fma.rn.f32x2 %0, %1, %2, %3;" : "=l"(d) : "l"(a), "l"(b), "l"(c)); return d;
}

// ---------------- Kernel 2: fused scan, merged delay line, deep prefetch ----
// Two timesteps per iteration. pair p = slots (2p+1, 2p+2), p = 0..31.
//   S''_p = S_{p+1} + Ae_p*y0 + Ao_p*y1 + Ce_p*u0 + Co_p*u1
// Warp = 8 sequences x 4 lanes; lane r owns pairs 8r..8r+7.
// u is read through an 8-slot register FIFO (prefetch distance 8 iterations
// = 16 timesteps ~ 700+ cycles) so DRAM latency is fully hidden.
#define PD 8   // prefetch depth (iterations); loop unrolled by PD

__global__ void __launch_bounds__(256, 1)
scan_kernel(const float* __restrict__ u, float* __restrict__ y) {
    int warp = blockIdx.x * (blockDim.x >> 5) + (threadIdx.x >> 5);
    int lane = threadIdx.x & 31;
    int g = lane >> 2;   // sequence within warp
    int r = lane & 3;    // lane within group
    int leader = lane & ~3;
    int seq = warp * 8 + g;           // 0..8191
    int h = seq & (HH - 1);
    const float* ubase = u + (size_t)seq * LL;
    float* ybase = y + (size_t)seq * LL;

    const float* ah = g_a + h * NN;
    const float* ch = g_c + h * NN;

    ull Ae[8], Ao[8], Ce[8], Co[8], S[8];
#pragma unroll
    for (int i = 0; i < 8; i++) {
        int p = r * 8 + i;
        int i1 = 2 * p + 1, i2 = 2 * p + 2, i3 = 2 * p + 3;
        // A'[idx] = a[idx-1] for 1<=idx<=64 ; C'[idx] = c[idx] for 1<=idx<=63
        float A1 = (i1 <= 64) ? ah[i1 - 1] : 0.f;
        float A2 = (i2 <= 64) ? ah[i2 - 1] : 0.f;
        float A3 = (i3 <= 64) ? ah[i3 - 1] : 0.f;
        float C1 = (i1 <= 63) ? ch[i1] : 0.f;
        float C2 = (i2 <= 63) ? ch[i2] : 0.f;
        float C3 = (i3 <= 63) ? ch[i3] : 0.f;
        Ae[i] = pack2(A2, A3);
        Ao[i] = pack2(A1, A2);
        Ce[i] = pack2(C2, C3);
        Co[i] = pack2(C1, C2);
        S[i] = 0ull;
    }
    float c0h = ch[0], c1h = ch[1], a0h = ah[0];
    float SS1 = 0.f, SS2 = 0.f;   // unpacked old S[0] (valid data on r==0)

    // prologue: fill FIFO with iterations 0..PD-1 (t = 0..2*PD-1)
    float2 buf[PD];
#pragma unroll
    for (int j = 0; j < PD; j++)
        buf[j] = *(const float2*)(ubase + 2 * j);

    for (int t0 = 0; t0 < LL; t0 += 2 * PD) {
#pragma unroll
        for (int j = 0; j < PD; j++) {
            int t = t0 + 2 * j;
            float2 cur = buf[j];
            // refill this slot for iteration t + 2*PD (clamped; unused if OOB)
            int tp = t + 2 * PD;
            if (tp >= LL) tp = 0;
            buf[j] = *(const float2*)(ubase + tp);

            // boundary pair from next lane (old S[0]); r==3 -> zero
            ull sn = __shfl_down_sync(0xffffffffu, S[0], 1);
            if (r == 3) sn = 0ull;

            float u0 = cur.x, u1 = cur.y;
            // every lane computes y from its own SS (garbage unless r==0),
            // then the group leader's value is broadcast
            float y0 = fmaf(c0h, u0, SS1);
            float y1 = fmaf(a0h, y0, fmaf(c1h, u0, fmaf(c0h, u1, SS2)));
            ull ypk = pack2(y0, y1);
            ypk = __shfl_sync(0xffffffffu, ypk, leader);
            float y0b, y1b; unpack2(ypk, y0b, y1b);
            ull y0pk = pack2(y0b, y0b), y1pk = pack2(y1b, y1b);
            ull u0pk = pack2(u0, u0), u1pk = pack2(u1, u1);

#pragma unroll
            for (int i = 0; i < 7; i++)
                S[i] = fma2(Ae[i], y0pk,
                        fma2(Ao[i], y1pk,
                         fma2(Ce[i], u0pk,
                          fma2(Co[i], u1pk, S[i + 1]))));
            S[7] = fma2(Ae[7], y0pk,
                     fma2(Ao[7], y1pk,
                      fma2(Ce[7], u0pk,
                       fma2(Co[7], u1pk, sn))));

            unpack2(S[0], SS1, SS2);

            if (r == 0) *(float2*)(ybase + t) = make_float2(y0, y1);
        }
    }
}

extern "C" void kernel_launch(void* const* d_in, const int* in_sizes, int n_in,
                              void* d_out, int out_size) {
    const float* u = (const float*)d_in[0];
    const float* k = (const float*)d_in[1];
    if (n_in >= 2 && in_sizes[0] == HH * NN) {  // defensive: swap if order differs
        u = (const float*)d_in[1];
        k = (const float*)d_in[0];
    }
    float* y = (float*)d_out;

    coef_kernel<<<HH, NN>>>(k);
    // 8192 sequences, 8 per warp, 8 warps per 256-thread CTA -> 128 CTAs
    scan_kernel<<<(BB * HH) / 64, 256>>>(u, y);
}